// round 16
// baseline (speedup 1.0000x reference)
#include <cuda_runtime.h>
#include <math.h>

#define NATOMS 1000
#define NPAIRS 10000
#define FDIM   64
#define NSH    9
#define YPAD   12
#define NL     3
#define NRBF   20
#define CUTOFF 5.0f
#define NITER  2
#define PCHUNK 64
#define PB     5

#define HDC __host__ __device__

// ---------------- device scratch (no allocations) -------------------------
__device__ float g_Y[NPAIRS * YPAD];
__device__ float g_Wij[NITER * NPAIRS * NL * FDIM];
__device__ float g_x1[NATOMS * NSH * FDIM];
__device__ float g_dx[NATOMS * NSH * FDIM];

// =================== compile-time real Clebsch-Gordan table ===============
HDC constexpr double cfact(int n) { double r = 1; for (int i = 2; i <= n; i++) r *= i; return r; }
HDC constexpr double csqrt_(double x) {
    if (x <= 0.0) return 0.0;
    double g = (x > 1.0) ? x : 1.0;
    for (int i = 0; i < 64; i++) g = 0.5 * (g + x / g);
    return g;
}
HDC constexpr int lof(int r) { return r >= 4 ? 2 : (r >= 1 ? 1 : 0); }

HDC constexpr double cg_c(int l1, int m1, int l2, int m2, int l3, int m3) {
    if (m3 != m1 + m2) return 0.0;
    int lmin = (l1 > l2) ? l1 - l2 : l2 - l1;
    if (l3 < lmin || l3 > l1 + l2) return 0.0;
    double pre = csqrt_((2.0 * l3 + 1.0) * cfact(l3 + l1 - l2) * cfact(l3 - l1 + l2) *
                        cfact(l1 + l2 - l3) / cfact(l1 + l2 + l3 + 1));
    pre *= csqrt_(cfact(l3 + m3) * cfact(l3 - m3) * cfact(l1 - m1) * cfact(l1 + m1) *
                  cfact(l2 - m2) * cfact(l2 + m2));
    double s = 0.0;
    for (int k = 0; k <= l1 + l2 - l3; k++) {
        int d2 = l1 - m1 - k, d3 = l2 + m2 - k, d4 = l3 - l2 + m1 + k, d5 = l3 - l1 - m2 + k;
        if (d2 < 0 || d3 < 0 || d4 < 0 || d5 < 0) continue;
        double denom = cfact(k) * cfact(l1 + l2 - l3 - k) * cfact(d2) * cfact(d3) *
                       cfact(d4) * cfact(d5);
        s += ((k & 1) ? -1.0 : 1.0) / denom;
    }
    return pre * s;
}

struct CRow { int n; int col[2]; double re[2]; double im[2]; };

HDC constexpr CRow urow(int r) {
    CRow s{}; int l = lof(r); int base = l * l + l; int mr = r - base;
    const double inv2 = 0.70710678118654752440;
    if (mr == 0) { s.n = 1; s.col[0] = base; s.re[0] = 1.0; s.im[0] = 0.0; }
    else if (mr > 0) {
        int m = mr; double sg = (m & 1) ? -1.0 : 1.0;
        s.n = 2;
        s.col[0] = base - m; s.re[0] = inv2;      s.im[0] = 0.0;
        s.col[1] = base + m; s.re[1] = sg * inv2; s.im[1] = 0.0;
    } else {
        int m = -mr; double sg = (m & 1) ? -1.0 : 1.0;
        s.n = 2;
        s.col[0] = base - m; s.re[0] = 0.0; s.im[0] = inv2;
        s.col[1] = base + m; s.re[1] = 0.0; s.im[1] = -sg * inv2;
    }
    return s;
}

HDC constexpr double real_cg(int o, int i2, int i3) {
    if (((lof(o) + lof(i2) + lof(i3)) & 1) != 0) return 0.0;
    CRow Ua = urow(i2), Ub = urow(i3), Uc = urow(o);
    int la = lof(i2), lb = lof(i3), lc = lof(o);
    int ba = la * la + la, bb = lb * lb + lb, bc = lc * lc + lc;
    double vre = 0.0;
    for (int i = 0; i < Ua.n; i++)
        for (int j = 0; j < Ub.n; j++)
            for (int k = 0; k < Uc.n; k++) {
                double cg = cg_c(la, Ua.col[i] - ba, lb, Ub.col[j] - bb, lc, Uc.col[k] - bc);
                if (cg == 0.0) continue;
                double t1r = Ua.re[i] * Ub.re[j] - Ua.im[i] * Ub.im[j];
                double t1i = Ua.re[i] * Ub.im[j] + Ua.im[i] * Ub.re[j];
                double tre = t1r * Uc.re[k] + t1i * Uc.im[k];
                vre += cg * tre;
            }
    return vre;
}

template <int LO, int HI>
struct Seg {
    static __device__ __forceinline__ void run(float (&acc)[9], const float (&a)[9],
                                               const float (&b)[9]) {
        if constexpr (HI - LO == 1) {
            constexpr int O = LO / 81, I2 = (LO / 9) % 9, I3 = LO % 9;
            constexpr double v = real_cg(O, I2, I3);
            if constexpr (v > 1e-9 || v < -1e-9) {
                acc[O] = fmaf((float)v, a[I2] * b[I3], acc[O]);
            }
        } else {
            Seg<LO, (LO + HI) / 2>::run(acc, a, b);
            Seg<(LO + HI) / 2, HI>::run(acc, a, b);
        }
    }
};

#define C0(o) ((float)real_cg(o, 0, o))

// ---- warp-parallel bound search over sorted idx_i ------------------------
__device__ __forceinline__ int warp_bound(const int* __restrict__ idx, int a, bool upper) {
    int lane = threadIdx.x & 31;
    int lo = 0, hiB = NPAIRS;
    while (hiB > lo) {
        int step = (hiB - lo + 31) >> 5;
        int pos = lo + lane * step;
        bool lt = false;
        if (pos < hiB) {
            int v = __ldg(idx + pos);
            lt = upper ? (v <= a) : (v < a);
        }
        unsigned m = __ballot_sync(0xffffffffu, lt);
        int c = __popc(m);
        if (c == 0) hiB = lo;
        else {
            int nlo = lo + (c - 1) * step + 1;
            int nhi = (c < 32) ? min(lo + c * step, hiB) : hiB;
            lo = nlo; hiB = nhi;
        }
    }
    return lo;
}

// ---------------- per-pair setup: Wf staged in transposed smem ------------
__global__ __launch_bounds__(256)
void pair_setup_kernel(const float* __restrict__ r_ij,
                       const float* __restrict__ Wf,
                       const float* __restrict__ bf) {
    __shared__ float4 s_w4[15 * 64];        // [(l*5+k4)*64 + f]
    __shared__ float  s_rad[PCHUNK][NRBF];
    __shared__ float  s_cut[PCHUNK];
    __shared__ float  s_d[PCHUNK];

    int t = blockIdx.y;
    int p0 = blockIdx.x * PCHUNK;
    int tid = threadIdx.x;
    int f = tid & 63;
    int slot = tid >> 6;

    // stage Wf[t] into smem transposed: s_w4[(l*5+k4)*64+f] = Wf[4k4..4k4+3][l][f]
    const float* wft = Wf + t * (NRBF * NL * FDIM);
    for (int i = tid; i < 15 * 64; i += 256) {
        int lk4 = i >> 6, ff = i & 63;
        int l = lk4 / 5, k4 = lk4 % 5;
        float4 v;
        v.x = __ldg(wft + (4 * k4 + 0) * 192 + l * 64 + ff);
        v.y = __ldg(wft + (4 * k4 + 1) * 192 + l * 64 + ff);
        v.z = __ldg(wft + (4 * k4 + 2) * 192 + l * 64 + ff);
        v.w = __ldg(wft + (4 * k4 + 3) * 192 + l * 64 + ff);
        s_w4[i] = v;
    }
    float bfl[NL];
    #pragma unroll
    for (int l = 0; l < NL; l++) bfl[l] = __ldg(bf + t * NL * FDIM + l * FDIM + f);

    if (tid < PCHUNK) {
        int p = p0 + tid;
        if (p < NPAIRS) {
            float rx = __ldg(r_ij + 3 * p), ry = __ldg(r_ij + 3 * p + 1),
                  rz = __ldg(r_ij + 3 * p + 2);
            float d = sqrtf(rx * rx + ry * ry + rz * rz);
            s_d[tid] = d;
            s_cut[tid] = (d < CUTOFF)
                       ? 0.5f * (cosf(d * (3.14159265358979323846f / CUTOFF)) + 1.f) : 0.f;
            if (blockIdx.y == 0) {
                float inv = 1.f / d;
                float x = rx * inv, y = ry * inv, z = rz * inv;
                const float c0 = 0.28209479177387814f;
                const float c1 = 0.4886025119029199f;
                const float c2 = 1.0925484305920792f;
                const float c3 = 0.31539156525252005f;
                const float c4 = 0.5462742152960396f;
                float4* yp = reinterpret_cast<float4*>(g_Y + p * YPAD);
                yp[0] = make_float4(c0, c1 * y, c1 * z, c1 * x);
                yp[1] = make_float4(c2 * x * y, c2 * y * z,
                                    c3 * (3.f * z * z - 1.f), c2 * x * z);
                yp[2] = make_float4(c4 * (x * x - y * y), 0.f, 0.f, 0.f);
            }
        }
    }
    __syncthreads();

    const float width = CUTOFF / (NRBF - 1);
    const float alpha = -0.5f / (width * width);
    for (int idx = tid; idx < PCHUNK * NRBF; idx += 256) {
        int pl = idx / NRBF, k = idx % NRBF;
        if (p0 + pl < NPAIRS) {
            float dd = s_d[pl] - width * (float)k;
            s_rad[pl][k] = __expf(alpha * dd * dd) * s_cut[pl];
        }
    }
    __syncthreads();

    float* wout = g_Wij + ((size_t)t * NPAIRS) * (NL * FDIM) + f;
    for (int pl = slot; pl < PCHUNK; pl += 4) {
        int p = p0 + pl;
        if (p >= NPAIRS) break;
        float cut = s_cut[pl];
        float acc[NL];
        #pragma unroll
        for (int l = 0; l < NL; l++) acc[l] = bfl[l] * cut;
        const float4* rp = reinterpret_cast<const float4*>(s_rad[pl]);
        #pragma unroll
        for (int k4 = 0; k4 < 5; k4++) {
            float4 r = rp[k4];
            #pragma unroll
            for (int l = 0; l < NL; l++) {
                float4 w = s_w4[(l * 5 + k4) * 64 + f];
                acc[l] = fmaf(r.x, w.x, acc[l]);
                acc[l] = fmaf(r.y, w.y, acc[l]);
                acc[l] = fmaf(r.z, w.z, acc[l]);
                acc[l] = fmaf(r.w, w.w, acc[l]);
            }
        }
        float* wp = wout + (size_t)p * (NL * FDIM);
        wp[0]   = acc[0];
        wp[64]  = acc[1];
        wp[128] = acc[2];
    }
}

// ---------------- update stage, 256 threads/atom (4-way k-split) ----------
// thread = (f, q): q in {0..3} owns k-range [q*16, q*16+16)
__device__ __forceinline__ void update_stage_q(
    int f, int q, int base,
    const float* __restrict__ W1, const float* __restrict__ W2,
    const float* __restrict__ W3, const float* __restrict__ Wg,
    const float* __restrict__ bg, int T,
    const float (&dxr)[9], const float (&prev)[9], float* __restrict__ xw,
    float* sbA, float* sbB, float* sbP) {

    const float* w1 = W1 + T * 4096 + f;
    const float* w2 = W2 + T * 4096 + f;
    const float* w3 = W3 + T * 4096 + f;
    const float* wg = Wg + T * 12288 + f;
    const float* bgp = bg + T * 192 + f;

    float w[16];

    // ---- GEMV1: ddx = dx @ W1 ----
    if (q == 0) {
        #pragma unroll
        for (int o = 0; o < 9; o++) sbA[o * 64 + f] = dxr[o];
    }
    #pragma unroll
    for (int k = 0; k < 16; k++) w[k] = __ldg(w1 + (q * 16 + k) * 64);
    __syncthreads();                         // B1
    {
        const float4* a4 = reinterpret_cast<const float4*>(sbA);
        #pragma unroll
        for (int o = 0; o < 9; o++) {
            float s = 0.f;
            #pragma unroll
            for (int k4 = 0; k4 < 4; k4++) {
                float4 v = a4[o * 16 + q * 4 + k4];
                s = fmaf(v.x, w[k4 * 4 + 0], s);
                s = fmaf(v.y, w[k4 * 4 + 1], s);
                s = fmaf(v.z, w[k4 * 4 + 2], s);
                s = fmaf(v.w, w[k4 * 4 + 3], s);
            }
            sbP[q * 576 + o * 64 + f] = s;
        }
    }
    __syncthreads();                         // B2
    float ddx[9];
    #pragma unroll
    for (int o = 0; o < 9; o++)
        ddx[o] = (sbP[o * 64 + f] + sbP[576 + o * 64 + f])
               + (sbP[1152 + o * 64 + f] + sbP[1728 + o * 64 + f]);

    // ---- tp = dx + CG(dx, ddx) (redundant in all quarters) ----
    float tp[9];
    #pragma unroll
    for (int o = 0; o < 9; o++) tp[o] = dxr[o];
    Seg<0, 729>::run(tp, dxr, ddx);

    if (q == 0) {
        #pragma unroll
        for (int o = 0; o < 9; o++) sbB[o * 64 + f] = tp[o];
    }
    #pragma unroll
    for (int k = 0; k < 16; k++) w[k] = __ldg(w2 + (q * 16 + k) * 64);
    __syncthreads();                         // B3
    // ---- GEMV2: dx2 = tp @ W2 ----
    {
        const float4* b4 = reinterpret_cast<const float4*>(sbB);
        #pragma unroll
        for (int o = 0; o < 9; o++) {
            float s = 0.f;
            #pragma unroll
            for (int k4 = 0; k4 < 4; k4++) {
                float4 v = b4[o * 16 + q * 4 + k4];
                s = fmaf(v.x, w[k4 * 4 + 0], s);
                s = fmaf(v.y, w[k4 * 4 + 1], s);
                s = fmaf(v.z, w[k4 * 4 + 2], s);
                s = fmaf(v.w, w[k4 * 4 + 3], s);
            }
            sbP[q * 576 + o * 64 + f] = s;
        }
    }
    __syncthreads();                         // B4
    float dx2[9];
    #pragma unroll
    for (int o = 0; o < 9; o++)
        dx2[o] = (sbP[o * 64 + f] + sbP[576 + o * 64 + f])
               + (sbP[1152 + o * 64 + f] + sbP[1728 + o * 64 + f]);

    // ---- gate = sigmoid(dx2[0,:] @ Wg + bg), k-split ----
    if (q == 0) sbA[f] = dx2[0];
    __syncthreads();                         // B5
    float g0 = 0.f, g1 = 0.f, g2 = 0.f;
    {
        const float4* r0 = reinterpret_cast<const float4*>(sbA);
        #pragma unroll
        for (int k4 = 0; k4 < 4; k4++) {
            float4 v = r0[q * 4 + k4];
            const float* wgk = wg + (q * 16 + k4 * 4) * 192;
            g0 = fmaf(v.x, __ldg(wgk), g0);
            g1 = fmaf(v.x, __ldg(wgk + 64), g1);
            g2 = fmaf(v.x, __ldg(wgk + 128), g2);
            g0 = fmaf(v.y, __ldg(wgk + 192), g0);
            g1 = fmaf(v.y, __ldg(wgk + 256), g1);
            g2 = fmaf(v.y, __ldg(wgk + 320), g2);
            g0 = fmaf(v.z, __ldg(wgk + 384), g0);
            g1 = fmaf(v.z, __ldg(wgk + 448), g1);
            g2 = fmaf(v.z, __ldg(wgk + 512), g2);
            g0 = fmaf(v.w, __ldg(wgk + 576), g0);
            g1 = fmaf(v.w, __ldg(wgk + 640), g1);
            g2 = fmaf(v.w, __ldg(wgk + 704), g2);
        }
    }
    sbP[q * 576 + 0 * 64 + f] = g0;
    sbP[q * 576 + 1 * 64 + f] = g1;
    sbP[q * 576 + 2 * 64 + f] = g2;
    __syncthreads();                         // B6
    float sg[3];
    #pragma unroll
    for (int l = 0; l < 3; l++) {
        float gs = (sbP[l * 64 + f] + sbP[576 + l * 64 + f])
                 + (sbP[1152 + l * 64 + f] + sbP[1728 + l * 64 + f]);
        sg[l] = 1.f / (1.f + __expf(-(gs + bgp[l * 64])));
    }

    if (q == 0) {
        #pragma unroll
        for (int o = 0; o < 9; o++) {
            int l = (o >= 4) ? 2 : ((o >= 1) ? 1 : 0);
            sbB[o * 64 + f] = dx2[o] * sg[l];
        }
    }
    #pragma unroll
    for (int k = 0; k < 16; k++) w[k] = __ldg(w3 + (q * 16 + k) * 64);
    __syncthreads();                         // B7
    // ---- GEMV3: out = gated @ W3 ----
    {
        const float4* b4 = reinterpret_cast<const float4*>(sbB);
        #pragma unroll
        for (int o = 0; o < 9; o++) {
            float s = 0.f;
            #pragma unroll
            for (int k4 = 0; k4 < 4; k4++) {
                float4 v = b4[o * 16 + q * 4 + k4];
                s = fmaf(v.x, w[k4 * 4 + 0], s);
                s = fmaf(v.y, w[k4 * 4 + 1], s);
                s = fmaf(v.z, w[k4 * 4 + 2], s);
                s = fmaf(v.w, w[k4 * 4 + 3], s);
            }
            sbP[q * 576 + o * 64 + f] = s;
        }
    }
    __syncthreads();                         // B8
    if (q == 0) {
        #pragma unroll
        for (int o = 0; o < 9; o++) {
            float s = (sbP[o * 64 + f] + sbP[576 + o * 64 + f])
                    + (sbP[1152 + o * 64 + f] + sbP[1728 + o * 64 + f]);
            xw[base + o * 64 + f] = prev[o] + s;
        }
    }
}

// ---------------- t0: message (scalar x, 4-way split) + update -----------
__global__ __launch_bounds__(256, 4)
void fused_t0(const int* __restrict__ idx_i, const int* __restrict__ idx_j,
              const int* __restrict__ Z, const float* __restrict__ emb,
              const float* __restrict__ W1, const float* __restrict__ W2,
              const float* __restrict__ W3, const float* __restrict__ Wg,
              const float* __restrict__ bg) {
    __shared__ float sbA[NSH * FDIM];
    __shared__ float sbB[NSH * FDIM];
    __shared__ float sbP[4 * NSH * FDIM];
    __shared__ int   s_seg[2];

    int tid = threadIdx.x;
    int f = tid & 63;
    int q = tid >> 6;
    int a = blockIdx.x;
    int base = a * (NSH * FDIM);

    for (int i = tid; i < NSH * FDIM; i += 256) g_dx[base + i] = 0.f;

    if (tid < 32) {
        int ps = warp_bound(idx_i, a, false);
        int pe = warp_bound(idx_i, a, true);
        if (tid == 0) { s_seg[0] = ps; s_seg[1] = pe; }
    }
    __syncthreads();
    int pstart = s_seg[0], pend = s_seg[1];

    float dxr[9];
    #pragma unroll
    for (int o = 0; o < 9; o++) dxr[o] = 0.f;

    const float* wbase = g_Wij + f;   // t = 0
    for (int p = pstart + q; p < pend; p += 4) {
        int j = __ldg(idx_j + p);
        float x0 = __ldg(emb + __ldg(Z + j) * FDIM + f);
        const float4* yp4 = reinterpret_cast<const float4*>(g_Y + p * YPAD);
        float4 y0 = yp4[0], y1 = yp4[1], y2 = yp4[2];
        const float* wp = wbase + (size_t)p * (NL * FDIM);
        float w0 = wp[0], w1v = wp[64], w2v = wp[128];
        dxr[0] = fmaf(C0(0) * x0, y0.x * w0,  dxr[0]);
        dxr[1] = fmaf(C0(1) * x0, y0.y * w1v, dxr[1]);
        dxr[2] = fmaf(C0(2) * x0, y0.z * w1v, dxr[2]);
        dxr[3] = fmaf(C0(3) * x0, y0.w * w1v, dxr[3]);
        dxr[4] = fmaf(C0(4) * x0, y1.x * w2v, dxr[4]);
        dxr[5] = fmaf(C0(5) * x0, y1.y * w2v, dxr[5]);
        dxr[6] = fmaf(C0(6) * x0, y1.z * w2v, dxr[6]);
        dxr[7] = fmaf(C0(7) * x0, y1.w * w2v, dxr[7]);
        dxr[8] = fmaf(C0(8) * x0, y2.x * w2v, dxr[8]);
    }
    // reduce quarters
    #pragma unroll
    for (int o = 0; o < 9; o++) sbP[q * 576 + o * 64 + f] = dxr[o];
    __syncthreads();
    #pragma unroll
    for (int o = 0; o < 9; o++)
        dxr[o] = (sbP[o * 64 + f] + sbP[576 + o * 64 + f])
               + (sbP[1152 + o * 64 + f] + sbP[1728 + o * 64 + f]);
    __syncthreads();

    float prev[9];
    prev[0] = __ldg(emb + __ldg(Z + a) * FDIM + f);
    #pragma unroll
    for (int o = 1; o < 9; o++) prev[o] = 0.f;

    update_stage_q(f, q, base, W1, W2, W3, Wg, bg, 0, dxr, prev, g_x1,
                   sbA, sbB, sbP);
}

// ---------------- msg1: pair-parallel CG message with run-length atomics ---
__global__ __launch_bounds__(64, 14)
void msg1_kernel(const int* __restrict__ idx_i, const int* __restrict__ idx_j) {
    int f = threadIdx.x;
    int p0 = blockIdx.x * PB;
    if (p0 >= NPAIRS) return;

    const float* wbase = g_Wij + (size_t)NPAIRS * (NL * FDIM) + f;   // t = 1

    float dxr[9];
    #pragma unroll
    for (int o = 0; o < 9; o++) dxr[o] = 0.f;
    int cur = __ldg(idx_i + p0);

    #pragma unroll
    for (int k = 0; k < PB; k++) {
        int p = p0 + k;
        if (p >= NPAIRS) break;
        int ai = __ldg(idx_i + p);
        if (ai != cur) {
            float* dp = g_dx + cur * (NSH * FDIM) + f;
            #pragma unroll
            for (int o = 0; o < 9; o++) {
                atomicAdd(dp + o * 64, dxr[o]);
                dxr[o] = 0.f;
            }
            cur = ai;
        }
        int j = __ldg(idx_j + p);
        const float4* yp4 = reinterpret_cast<const float4*>(g_Y + p * YPAD);
        float4 y0 = yp4[0], y1 = yp4[1], y2 = yp4[2];
        const float* wp = wbase + (size_t)p * (NL * FDIM);
        float w0 = wp[0], w1v = wp[64], w2v = wp[128];
        float tv[9];
        tv[0] = y0.x * w0;
        tv[1] = y0.y * w1v;
        tv[2] = y0.z * w1v;
        tv[3] = y0.w * w1v;
        tv[4] = y1.x * w2v;
        tv[5] = y1.y * w2v;
        tv[6] = y1.z * w2v;
        tv[7] = y1.w * w2v;
        tv[8] = y2.x * w2v;
        const float* xj = g_x1 + j * (NSH * FDIM) + f;
        float xr[9];
        #pragma unroll
        for (int o = 0; o < 9; o++) xr[o] = __ldg(xj + o * 64);
        Seg<0, 729>::run(dxr, xr, tv);
    }
    {
        float* dp = g_dx + cur * (NSH * FDIM) + f;
        #pragma unroll
        for (int o = 0; o < 9; o++) atomicAdd(dp + o * 64, dxr[o]);
    }
}

// ---------------- upd1: update-only from g_dx (256 threads/atom) -----------
__global__ __launch_bounds__(256, 4)
void upd1_kernel(float* __restrict__ xout,
                 const float* __restrict__ W1, const float* __restrict__ W2,
                 const float* __restrict__ W3, const float* __restrict__ Wg,
                 const float* __restrict__ bg) {
    __shared__ float sbA[NSH * FDIM];
    __shared__ float sbB[NSH * FDIM];
    __shared__ float sbP[4 * NSH * FDIM];
    int tid = threadIdx.x;
    int f = tid & 63;
    int q = tid >> 6;
    int a = blockIdx.x;
    int base = a * (NSH * FDIM);

    float dxr[9], prev[9];
    #pragma unroll
    for (int o = 0; o < 9; o++) {
        dxr[o]  = g_dx[base + o * 64 + f];
        prev[o] = __ldg(g_x1 + base + o * 64 + f);
    }
    update_stage_q(f, q, base, W1, W2, W3, Wg, bg, 1, dxr, prev, xout,
                   sbA, sbB, sbP);
}

// ---------------- launch ---------------------------------------------------
extern "C" void kernel_launch(void* const* d_in, const int* in_sizes, int n_in,
                              void* d_out, int out_size) {
    const int*   Z    = (const int*)d_in[0];
    const float* r_ij = (const float*)d_in[1];
    const int*   idxi = (const int*)d_in[2];
    const int*   idxj = (const int*)d_in[3];
    const float* emb  = (const float*)d_in[4];
    const float* Wf   = (const float*)d_in[5];
    const float* bf   = (const float*)d_in[6];
    const float* W1   = (const float*)d_in[7];
    const float* W2   = (const float*)d_in[8];
    const float* W3   = (const float*)d_in[9];
    const float* Wg   = (const float*)d_in[10];
    const float* bg   = (const float*)d_in[11];
    float* xout = (float*)d_out;

    dim3 psgrid((NPAIRS + PCHUNK - 1) / PCHUNK, NITER);
    pair_setup_kernel<<<psgrid, 256>>>(r_ij, Wf, bf);
    fused_t0<<<NATOMS, 256>>>(idxi, idxj, Z, emb, W1, W2, W3, Wg, bg);
    msg1_kernel<<<(NPAIRS + PB - 1) / PB, 64>>>(idxi, idxj);
    upd1_kernel<<<NATOMS, 256>>>(xout, W1, W2, W3, Wg, bg);
}

// round 17
// speedup vs baseline: 1.3323x; 1.3323x over previous
#include <cuda_runtime.h>
#include <math.h>

#define NATOMS 1000
#define NPAIRS 10000
#define FDIM   64
#define NSH    9
#define YPAD   12
#define NL     3
#define NRBF   20
#define CUTOFF 5.0f
#define NITER  2
#define PCHUNK 64
#define PB     5

#define HDC __host__ __device__

// ---------------- device scratch (no allocations) -------------------------
__device__ float g_Y[NPAIRS * YPAD];
__device__ float g_Wij[NITER * NPAIRS * NL * FDIM];
__device__ float g_x1[NATOMS * NSH * FDIM];
__device__ float g_dx[NATOMS * NSH * FDIM];

// =================== compile-time real Clebsch-Gordan table ===============
HDC constexpr double cfact(int n) { double r = 1; for (int i = 2; i <= n; i++) r *= i; return r; }
HDC constexpr double csqrt_(double x) {
    if (x <= 0.0) return 0.0;
    double g = (x > 1.0) ? x : 1.0;
    for (int i = 0; i < 64; i++) g = 0.5 * (g + x / g);
    return g;
}
HDC constexpr int lof(int r) { return r >= 4 ? 2 : (r >= 1 ? 1 : 0); }

HDC constexpr double cg_c(int l1, int m1, int l2, int m2, int l3, int m3) {
    if (m3 != m1 + m2) return 0.0;
    int lmin = (l1 > l2) ? l1 - l2 : l2 - l1;
    if (l3 < lmin || l3 > l1 + l2) return 0.0;
    double pre = csqrt_((2.0 * l3 + 1.0) * cfact(l3 + l1 - l2) * cfact(l3 - l1 + l2) *
                        cfact(l1 + l2 - l3) / cfact(l1 + l2 + l3 + 1));
    pre *= csqrt_(cfact(l3 + m3) * cfact(l3 - m3) * cfact(l1 - m1) * cfact(l1 + m1) *
                  cfact(l2 - m2) * cfact(l2 + m2));
    double s = 0.0;
    for (int k = 0; k <= l1 + l2 - l3; k++) {
        int d2 = l1 - m1 - k, d3 = l2 + m2 - k, d4 = l3 - l2 + m1 + k, d5 = l3 - l1 - m2 + k;
        if (d2 < 0 || d3 < 0 || d4 < 0 || d5 < 0) continue;
        double denom = cfact(k) * cfact(l1 + l2 - l3 - k) * cfact(d2) * cfact(d3) *
                       cfact(d4) * cfact(d5);
        s += ((k & 1) ? -1.0 : 1.0) / denom;
    }
    return pre * s;
}

struct CRow { int n; int col[2]; double re[2]; double im[2]; };

HDC constexpr CRow urow(int r) {
    CRow s{}; int l = lof(r); int base = l * l + l; int mr = r - base;
    const double inv2 = 0.70710678118654752440;
    if (mr == 0) { s.n = 1; s.col[0] = base; s.re[0] = 1.0; s.im[0] = 0.0; }
    else if (mr > 0) {
        int m = mr; double sg = (m & 1) ? -1.0 : 1.0;
        s.n = 2;
        s.col[0] = base - m; s.re[0] = inv2;      s.im[0] = 0.0;
        s.col[1] = base + m; s.re[1] = sg * inv2; s.im[1] = 0.0;
    } else {
        int m = -mr; double sg = (m & 1) ? -1.0 : 1.0;
        s.n = 2;
        s.col[0] = base - m; s.re[0] = 0.0; s.im[0] = inv2;
        s.col[1] = base + m; s.re[1] = 0.0; s.im[1] = -sg * inv2;
    }
    return s;
}

HDC constexpr double real_cg(int o, int i2, int i3) {
    if (((lof(o) + lof(i2) + lof(i3)) & 1) != 0) return 0.0;
    CRow Ua = urow(i2), Ub = urow(i3), Uc = urow(o);
    int la = lof(i2), lb = lof(i3), lc = lof(o);
    int ba = la * la + la, bb = lb * lb + lb, bc = lc * lc + lc;
    double vre = 0.0;
    for (int i = 0; i < Ua.n; i++)
        for (int j = 0; j < Ub.n; j++)
            for (int k = 0; k < Uc.n; k++) {
                double cg = cg_c(la, Ua.col[i] - ba, lb, Ub.col[j] - bb, lc, Uc.col[k] - bc);
                if (cg == 0.0) continue;
                double t1r = Ua.re[i] * Ub.re[j] - Ua.im[i] * Ub.im[j];
                double t1i = Ua.re[i] * Ub.im[j] + Ua.im[i] * Ub.re[j];
                double tre = t1r * Uc.re[k] + t1i * Uc.im[k];
                vre += cg * tre;
            }
    return vre;
}

template <int LO, int HI>
struct Seg {
    static __device__ __forceinline__ void run(float (&acc)[9], const float (&a)[9],
                                               const float (&b)[9]) {
        if constexpr (HI - LO == 1) {
            constexpr int O = LO / 81, I2 = (LO / 9) % 9, I3 = LO % 9;
            constexpr double v = real_cg(O, I2, I3);
            if constexpr (v > 1e-9 || v < -1e-9) {
                acc[O] = fmaf((float)v, a[I2] * b[I3], acc[O]);
            }
        } else {
            Seg<LO, (LO + HI) / 2>::run(acc, a, b);
            Seg<(LO + HI) / 2, HI>::run(acc, a, b);
        }
    }
};

#define C0(o) ((float)real_cg(o, 0, o))

// ---- warp-parallel bound search over sorted idx_i ------------------------
__device__ __forceinline__ int warp_bound(const int* __restrict__ idx, int a, bool upper) {
    int lane = threadIdx.x & 31;
    int lo = 0, hiB = NPAIRS;
    while (hiB > lo) {
        int step = (hiB - lo + 31) >> 5;
        int pos = lo + lane * step;
        bool lt = false;
        if (pos < hiB) {
            int v = __ldg(idx + pos);
            lt = upper ? (v <= a) : (v < a);
        }
        unsigned m = __ballot_sync(0xffffffffu, lt);
        int c = __popc(m);
        if (c == 0) hiB = lo;
        else {
            int nlo = lo + (c - 1) * step + 1;
            int nhi = (c < 32) ? min(lo + c * step, hiB) : hiB;
            lo = nlo; hiB = nhi;
        }
    }
    return lo;
}

// ---------------- per-pair setup: blocked GEMM, Wf in registers -----------
__global__ __launch_bounds__(256)
void pair_setup_kernel(const float* __restrict__ r_ij,
                       const float* __restrict__ Wf,
                       const float* __restrict__ bf) {
    __shared__ float s_rad[PCHUNK][NRBF];
    __shared__ float s_cut[PCHUNK];
    __shared__ float s_d[PCHUNK];

    int t = blockIdx.y;
    int p0 = blockIdx.x * PCHUNK;
    int tid = threadIdx.x;
    int f = tid & 63;
    int slot = tid >> 6;

    float w[NL][NRBF];
    const float* wf = Wf + t * (NRBF * NL * FDIM) + f;
    #pragma unroll
    for (int k = 0; k < NRBF; k++)
        #pragma unroll
        for (int l = 0; l < NL; l++)
            w[l][k] = __ldg(wf + k * NL * FDIM + l * FDIM);
    float bfl[NL];
    #pragma unroll
    for (int l = 0; l < NL; l++) bfl[l] = __ldg(bf + t * NL * FDIM + l * FDIM + f);

    if (tid < PCHUNK) {
        int p = p0 + tid;
        if (p < NPAIRS) {
            float rx = __ldg(r_ij + 3 * p), ry = __ldg(r_ij + 3 * p + 1),
                  rz = __ldg(r_ij + 3 * p + 2);
            float d = sqrtf(rx * rx + ry * ry + rz * rz);
            s_d[tid] = d;
            s_cut[tid] = (d < CUTOFF)
                       ? 0.5f * (cosf(d * (3.14159265358979323846f / CUTOFF)) + 1.f) : 0.f;
            if (blockIdx.y == 0) {
                float inv = 1.f / d;
                float x = rx * inv, y = ry * inv, z = rz * inv;
                const float c0 = 0.28209479177387814f;
                const float c1 = 0.4886025119029199f;
                const float c2 = 1.0925484305920792f;
                const float c3 = 0.31539156525252005f;
                const float c4 = 0.5462742152960396f;
                float4* yp = reinterpret_cast<float4*>(g_Y + p * YPAD);
                yp[0] = make_float4(c0, c1 * y, c1 * z, c1 * x);
                yp[1] = make_float4(c2 * x * y, c2 * y * z,
                                    c3 * (3.f * z * z - 1.f), c2 * x * z);
                yp[2] = make_float4(c4 * (x * x - y * y), 0.f, 0.f, 0.f);
            }
        }
    }
    __syncthreads();

    const float width = CUTOFF / (NRBF - 1);
    const float alpha = -0.5f / (width * width);
    for (int idx = tid; idx < PCHUNK * NRBF; idx += 256) {
        int pl = idx / NRBF, k = idx % NRBF;
        if (p0 + pl < NPAIRS) {
            float dd = s_d[pl] - width * (float)k;
            s_rad[pl][k] = __expf(alpha * dd * dd) * s_cut[pl];
        }
    }
    __syncthreads();

    float* wout = g_Wij + ((size_t)t * NPAIRS) * (NL * FDIM) + f;
    for (int pl = slot; pl < PCHUNK; pl += 4) {
        int p = p0 + pl;
        if (p >= NPAIRS) break;
        float cut = s_cut[pl];
        float s0 = bfl[0] * cut, s1 = bfl[1] * cut, s2 = bfl[2] * cut;
        const float4* rp = reinterpret_cast<const float4*>(s_rad[pl]);
        #pragma unroll
        for (int k4 = 0; k4 < 5; k4++) {
            float4 r = rp[k4];
            s0 = fmaf(r.x, w[0][k4 * 4 + 0], s0);
            s1 = fmaf(r.x, w[1][k4 * 4 + 0], s1);
            s2 = fmaf(r.x, w[2][k4 * 4 + 0], s2);
            s0 = fmaf(r.y, w[0][k4 * 4 + 1], s0);
            s1 = fmaf(r.y, w[1][k4 * 4 + 1], s1);
            s2 = fmaf(r.y, w[2][k4 * 4 + 1], s2);
            s0 = fmaf(r.z, w[0][k4 * 4 + 2], s0);
            s1 = fmaf(r.z, w[1][k4 * 4 + 2], s1);
            s2 = fmaf(r.z, w[2][k4 * 4 + 2], s2);
            s0 = fmaf(r.w, w[0][k4 * 4 + 3], s0);
            s1 = fmaf(r.w, w[1][k4 * 4 + 3], s1);
            s2 = fmaf(r.w, w[2][k4 * 4 + 3], s2);
        }
        float* wp = wout + (size_t)p * (NL * FDIM);
        wp[0]   = s0;
        wp[64]  = s1;
        wp[128] = s2;
    }
}

// ---------------- update stage, 128 threads/atom (2-way k-split) ----------
// thread = (f, h): h in {0,1} owns k-range [h*32, h*32+32)
// Staging/final writes distributed across halves by o-parity.
__device__ __forceinline__ void update_stage_h(
    int f, int h, int base,
    const float* __restrict__ W1, const float* __restrict__ W2,
    const float* __restrict__ W3, const float* __restrict__ Wg,
    const float* __restrict__ bg, int T,
    const float (&dxr)[9], const float (&prev)[9], float* __restrict__ xw,
    float* sbA, float* sbB, float* sbP) {

    const float* w1 = W1 + T * 4096 + f;
    const float* w2 = W2 + T * 4096 + f;
    const float* w3 = W3 + T * 4096 + f;
    const float* wg = Wg + T * 12288 + f;
    const float* bgp = bg + T * 192 + f;

    float w[32];

    // ---- GEMV1: ddx = dx @ W1 ----
    #pragma unroll
    for (int o = 0; o < 9; o++)
        if ((o & 1) == h) sbA[o * 64 + f] = dxr[o];
    #pragma unroll
    for (int k = 0; k < 32; k++) w[k] = __ldg(w1 + (h * 32 + k) * 64);
    __syncthreads();
    {
        const float4* a4 = reinterpret_cast<const float4*>(sbA);
        #pragma unroll
        for (int o = 0; o < 9; o++) {
            float s = 0.f;
            #pragma unroll
            for (int k4 = 0; k4 < 8; k4++) {
                float4 v = a4[o * 16 + h * 8 + k4];
                s = fmaf(v.x, w[k4 * 4 + 0], s);
                s = fmaf(v.y, w[k4 * 4 + 1], s);
                s = fmaf(v.z, w[k4 * 4 + 2], s);
                s = fmaf(v.w, w[k4 * 4 + 3], s);
            }
            sbP[h * 576 + o * 64 + f] = s;
        }
    }
    __syncthreads();
    float ddx[9];
    #pragma unroll
    for (int o = 0; o < 9; o++) ddx[o] = sbP[o * 64 + f] + sbP[576 + o * 64 + f];

    // ---- tp = dx + CG(dx, ddx) (redundant in both halves) ----
    float tp[9];
    #pragma unroll
    for (int o = 0; o < 9; o++) tp[o] = dxr[o];
    Seg<0, 729>::run(tp, dxr, ddx);

    // ---- GEMV2: dx2 = tp @ W2 ----
    #pragma unroll
    for (int o = 0; o < 9; o++)
        if ((o & 1) == h) sbB[o * 64 + f] = tp[o];
    #pragma unroll
    for (int k = 0; k < 32; k++) w[k] = __ldg(w2 + (h * 32 + k) * 64);
    __syncthreads();
    {
        const float4* b4 = reinterpret_cast<const float4*>(sbB);
        #pragma unroll
        for (int o = 0; o < 9; o++) {
            float s = 0.f;
            #pragma unroll
            for (int k4 = 0; k4 < 8; k4++) {
                float4 v = b4[o * 16 + h * 8 + k4];
                s = fmaf(v.x, w[k4 * 4 + 0], s);
                s = fmaf(v.y, w[k4 * 4 + 1], s);
                s = fmaf(v.z, w[k4 * 4 + 2], s);
                s = fmaf(v.w, w[k4 * 4 + 3], s);
            }
            sbP[h * 576 + o * 64 + f] = s;
        }
    }
    __syncthreads();
    float dx2[9];
    #pragma unroll
    for (int o = 0; o < 9; o++) dx2[o] = sbP[o * 64 + f] + sbP[576 + o * 64 + f];

    // ---- gate = sigmoid(dx2[0,:] @ Wg + bg), k-split ----
    if (h == 0) sbA[f] = dx2[0];
    __syncthreads();
    float g0 = 0.f, g1 = 0.f, g2 = 0.f;
    {
        const float4* r0 = reinterpret_cast<const float4*>(sbA);
        #pragma unroll
        for (int k4 = 0; k4 < 8; k4++) {
            float4 v = r0[h * 8 + k4];
            const float* wgk = wg + (h * 32 + k4 * 4) * 192;
            g0 = fmaf(v.x, __ldg(wgk), g0);
            g1 = fmaf(v.x, __ldg(wgk + 64), g1);
            g2 = fmaf(v.x, __ldg(wgk + 128), g2);
            g0 = fmaf(v.y, __ldg(wgk + 192), g0);
            g1 = fmaf(v.y, __ldg(wgk + 256), g1);
            g2 = fmaf(v.y, __ldg(wgk + 320), g2);
            g0 = fmaf(v.z, __ldg(wgk + 384), g0);
            g1 = fmaf(v.z, __ldg(wgk + 448), g1);
            g2 = fmaf(v.z, __ldg(wgk + 512), g2);
            g0 = fmaf(v.w, __ldg(wgk + 576), g0);
            g1 = fmaf(v.w, __ldg(wgk + 640), g1);
            g2 = fmaf(v.w, __ldg(wgk + 704), g2);
        }
    }
    sbP[h * 576 + 0 * 64 + f] = g0;
    sbP[h * 576 + 1 * 64 + f] = g1;
    sbP[h * 576 + 2 * 64 + f] = g2;
    __syncthreads();
    float sg[3];
    sg[0] = 1.f / (1.f + __expf(-(sbP[0 * 64 + f] + sbP[576 + 0 * 64 + f] + bgp[0])));
    sg[1] = 1.f / (1.f + __expf(-(sbP[1 * 64 + f] + sbP[576 + 1 * 64 + f] + bgp[64])));
    sg[2] = 1.f / (1.f + __expf(-(sbP[2 * 64 + f] + sbP[576 + 2 * 64 + f] + bgp[128])));

    // ---- GEMV3: out = (dx2 * sg[l]) @ W3 ; xw = prev + out ----
    __syncthreads();   // sbB reads (GEMV2) done; safe to overwrite
    #pragma unroll
    for (int o = 0; o < 9; o++) {
        if ((o & 1) == h) {
            int l = (o >= 4) ? 2 : ((o >= 1) ? 1 : 0);
            sbB[o * 64 + f] = dx2[o] * sg[l];
        }
    }
    #pragma unroll
    for (int k = 0; k < 32; k++) w[k] = __ldg(w3 + (h * 32 + k) * 64);
    __syncthreads();
    {
        const float4* b4 = reinterpret_cast<const float4*>(sbB);
        #pragma unroll
        for (int o = 0; o < 9; o++) {
            float s = 0.f;
            #pragma unroll
            for (int k4 = 0; k4 < 8; k4++) {
                float4 v = b4[o * 16 + h * 8 + k4];
                s = fmaf(v.x, w[k4 * 4 + 0], s);
                s = fmaf(v.y, w[k4 * 4 + 1], s);
                s = fmaf(v.z, w[k4 * 4 + 2], s);
                s = fmaf(v.w, w[k4 * 4 + 3], s);
            }
            sbP[h * 576 + o * 64 + f] = s;
        }
    }
    __syncthreads();
    #pragma unroll
    for (int o = 0; o < 9; o++) {
        if ((o & 1) == h)
            xw[base + o * 64 + f] = prev[o] + sbP[o * 64 + f] + sbP[576 + o * 64 + f];
    }
}

// ---------------- t0: message (scalar x, split by half) + update ----------
__global__ __launch_bounds__(128, 8)
void fused_t0(const int* __restrict__ idx_i, const int* __restrict__ idx_j,
              const int* __restrict__ Z, const float* __restrict__ emb,
              const float* __restrict__ W1, const float* __restrict__ W2,
              const float* __restrict__ W3, const float* __restrict__ Wg,
              const float* __restrict__ bg) {
    __shared__ float sbA[NSH * FDIM];
    __shared__ float sbB[NSH * FDIM];
    __shared__ float sbP[2 * NSH * FDIM];
    __shared__ int   s_seg[2];

    int tid = threadIdx.x;
    int f = tid & 63;
    int h = tid >> 6;
    int a = blockIdx.x;
    int base = a * (NSH * FDIM);

    for (int i = tid; i < NSH * FDIM; i += 128) g_dx[base + i] = 0.f;

    if (tid < 32) {
        int ps = warp_bound(idx_i, a, false);
        int pe = warp_bound(idx_i, a, true);
        if (tid == 0) { s_seg[0] = ps; s_seg[1] = pe; }
    }
    __syncthreads();
    int pstart = s_seg[0], pend = s_seg[1];

    float dxr[9];
    #pragma unroll
    for (int o = 0; o < 9; o++) dxr[o] = 0.f;

    const float* wbase = g_Wij + f;   // t = 0
    for (int p = pstart + h; p < pend; p += 2) {
        int j = __ldg(idx_j + p);
        float x0 = __ldg(emb + __ldg(Z + j) * FDIM + f);
        const float4* yp4 = reinterpret_cast<const float4*>(g_Y + p * YPAD);
        float4 y0 = yp4[0], y1 = yp4[1], y2 = yp4[2];
        const float* wp = wbase + (size_t)p * (NL * FDIM);
        float w0 = wp[0], w1v = wp[64], w2v = wp[128];
        dxr[0] = fmaf(C0(0) * x0, y0.x * w0,  dxr[0]);
        dxr[1] = fmaf(C0(1) * x0, y0.y * w1v, dxr[1]);
        dxr[2] = fmaf(C0(2) * x0, y0.z * w1v, dxr[2]);
        dxr[3] = fmaf(C0(3) * x0, y0.w * w1v, dxr[3]);
        dxr[4] = fmaf(C0(4) * x0, y1.x * w2v, dxr[4]);
        dxr[5] = fmaf(C0(5) * x0, y1.y * w2v, dxr[5]);
        dxr[6] = fmaf(C0(6) * x0, y1.z * w2v, dxr[6]);
        dxr[7] = fmaf(C0(7) * x0, y1.w * w2v, dxr[7]);
        dxr[8] = fmaf(C0(8) * x0, y2.x * w2v, dxr[8]);
    }
    #pragma unroll
    for (int o = 0; o < 9; o++) sbP[h * 576 + o * 64 + f] = dxr[o];
    __syncthreads();
    #pragma unroll
    for (int o = 0; o < 9; o++) dxr[o] = sbP[o * 64 + f] + sbP[576 + o * 64 + f];
    __syncthreads();

    float prev[9];
    prev[0] = __ldg(emb + __ldg(Z + a) * FDIM + f);
    #pragma unroll
    for (int o = 1; o < 9; o++) prev[o] = 0.f;

    update_stage_h(f, h, base, W1, W2, W3, Wg, bg, 0, dxr, prev, g_x1,
                   sbA, sbB, sbP);
}

// ---------------- msg1: pair-parallel CG message with run-length atomics ---
__global__ __launch_bounds__(64, 14)
void msg1_kernel(const int* __restrict__ idx_i, const int* __restrict__ idx_j) {
    int f = threadIdx.x;
    int p0 = blockIdx.x * PB;
    if (p0 >= NPAIRS) return;

    const float* wbase = g_Wij + (size_t)NPAIRS * (NL * FDIM) + f;   // t = 1

    float dxr[9];
    #pragma unroll
    for (int o = 0; o < 9; o++) dxr[o] = 0.f;
    int cur = __ldg(idx_i + p0);

    #pragma unroll
    for (int k = 0; k < PB; k++) {
        int p = p0 + k;
        if (p >= NPAIRS) break;
        int ai = __ldg(idx_i + p);
        if (ai != cur) {
            float* dp = g_dx + cur * (NSH * FDIM) + f;
            #pragma unroll
            for (int o = 0; o < 9; o++) {
                atomicAdd(dp + o * 64, dxr[o]);
                dxr[o] = 0.f;
            }
            cur = ai;
        }
        int j = __ldg(idx_j + p);
        const float4* yp4 = reinterpret_cast<const float4*>(g_Y + p * YPAD);
        float4 y0 = yp4[0], y1 = yp4[1], y2 = yp4[2];
        const float* wp = wbase + (size_t)p * (NL * FDIM);
        float w0 = wp[0], w1v = wp[64], w2v = wp[128];
        float tv[9];
        tv[0] = y0.x * w0;
        tv[1] = y0.y * w1v;
        tv[2] = y0.z * w1v;
        tv[3] = y0.w * w1v;
        tv[4] = y1.x * w2v;
        tv[5] = y1.y * w2v;
        tv[6] = y1.z * w2v;
        tv[7] = y1.w * w2v;
        tv[8] = y2.x * w2v;
        const float* xj = g_x1 + j * (NSH * FDIM) + f;
        float xr[9];
        #pragma unroll
        for (int o = 0; o < 9; o++) xr[o] = __ldg(xj + o * 64);
        Seg<0, 729>::run(dxr, xr, tv);
    }
    {
        float* dp = g_dx + cur * (NSH * FDIM) + f;
        #pragma unroll
        for (int o = 0; o < 9; o++) atomicAdd(dp + o * 64, dxr[o]);
    }
}

// ---------------- upd1: update-only from g_dx (128 threads/atom) -----------
__global__ __launch_bounds__(128, 8)
void upd1_kernel(float* __restrict__ xout,
                 const float* __restrict__ W1, const float* __restrict__ W2,
                 const float* __restrict__ W3, const float* __restrict__ Wg,
                 const float* __restrict__ bg) {
    __shared__ float sbA[NSH * FDIM];
    __shared__ float sbB[NSH * FDIM];
    __shared__ float sbP[2 * NSH * FDIM];
    int tid = threadIdx.x;
    int f = tid & 63;
    int h = tid >> 6;
    int a = blockIdx.x;
    int base = a * (NSH * FDIM);

    float dxr[9], prev[9];
    #pragma unroll
    for (int o = 0; o < 9; o++) {
        dxr[o]  = g_dx[base + o * 64 + f];
        prev[o] = __ldg(g_x1 + base + o * 64 + f);
    }
    update_stage_h(f, h, base, W1, W2, W3, Wg, bg, 1, dxr, prev, xout,
                   sbA, sbB, sbP);
}

// ---------------- launch ---------------------------------------------------
extern "C" void kernel_launch(void* const* d_in, const int* in_sizes, int n_in,
                              void* d_out, int out_size) {
    const int*   Z    = (const int*)d_in[0];
    const float* r_ij = (const float*)d_in[1];
    const int*   idxi = (const int*)d_in[2];
    const int*   idxj = (const int*)d_in[3];
    const float* emb  = (const float*)d_in[4];
    const float* Wf   = (const float*)d_in[5];
    const float* bf   = (const float*)d_in[6];
    const float* W1   = (const float*)d_in[7];
    const float* W2   = (const float*)d_in[8];
    const float* W3   = (const float*)d_in[9];
    const float* Wg   = (const float*)d_in[10];
    const float* bg   = (const float*)d_in[11];
    float* xout = (float*)d_out;

    dim3 psgrid((NPAIRS + PCHUNK - 1) / PCHUNK, NITER);
    pair_setup_kernel<<<psgrid, 256>>>(r_ij, Wf, bf);
    fused_t0<<<NATOMS, 128>>>(idxi, idxj, Z, emb, W1, W2, W3, Wg, bg);
    msg1_kernel<<<(NPAIRS + PB - 1) / PB, 64>>>(idxi, idxj);
    upd1_kernel<<<NATOMS, 128>>>(xout, W1, W2, W3, Wg, bg);
}